// round 1
// baseline (speedup 1.0000x reference)
#include <cuda_runtime.h>
#include <math.h>

// Problem dims (fixed per reference)
#define NROWS 16384
#define IND   512
#define HIDD  256
#define OD    128

// Scratch (device globals; no allocations allowed)
__device__ float g_h1[NROWS * HIDD];   // after linear1 + leaky
__device__ float g_h [NROWS * OD];     // after linear2 (attention input)

// ---------------------------------------------------------------------------
// Generic tiled SGEMM: C[M,N] = A[M,K] @ B[K,N] + bias, optional LeakyReLU.
// BM=BN=64, BK=16, 256 threads, 4x4 micro-tile with strided columns.
// ---------------------------------------------------------------------------
template<bool LEAKY>
__global__ __launch_bounds__(256) void gemm_bias_kernel(
    const float* __restrict__ A, const float* __restrict__ B,
    const float* __restrict__ bias, float* __restrict__ C,
    int M, int N, int K)
{
    __shared__ float As[16][65];   // [k][m], padded
    __shared__ float Bs[16][64];   // [k][n]

    const int tid = threadIdx.x;
    const int ty = tid >> 4, tx = tid & 15;
    const int m0 = blockIdx.y * 64, n0 = blockIdx.x * 64;

    float acc[4][4];
    #pragma unroll
    for (int i = 0; i < 4; i++)
        #pragma unroll
        for (int j = 0; j < 4; j++) acc[i][j] = 0.f;

    const int ar = tid >> 2, ak = (tid & 3) << 2;   // A tile: 64 rows x 16 k
    const int bk = tid >> 4, bn = (tid & 15) << 2;  // B tile: 16 k x 64 n

    for (int k0 = 0; k0 < K; k0 += 16) {
        float4 av = *(const float4*)(A + (size_t)(m0 + ar) * K + k0 + ak);
        As[ak + 0][ar] = av.x;
        As[ak + 1][ar] = av.y;
        As[ak + 2][ar] = av.z;
        As[ak + 3][ar] = av.w;
        float4 bv = *(const float4*)(B + (size_t)(k0 + bk) * N + n0 + bn);
        *(float4*)&Bs[bk][bn] = bv;
        __syncthreads();

        #pragma unroll
        for (int k = 0; k < 16; k++) {
            float ra[4], rb[4];
            #pragma unroll
            for (int i = 0; i < 4; i++) ra[i] = As[k][ty * 4 + i];
            #pragma unroll
            for (int j = 0; j < 4; j++) rb[j] = Bs[k][tx + 16 * j];
            #pragma unroll
            for (int i = 0; i < 4; i++)
                #pragma unroll
                for (int j = 0; j < 4; j++)
                    acc[i][j] = fmaf(ra[i], rb[j], acc[i][j]);
        }
        __syncthreads();
    }

    #pragma unroll
    for (int j = 0; j < 4; j++) {
        int c = n0 + tx + 16 * j;
        float bb = bias[c];
        #pragma unroll
        for (int i = 0; i < 4; i++) {
            int r = m0 + ty * 4 + i;
            float v = acc[i][j] + bb;
            if (LEAKY) v = (v >= 0.f) ? v : 0.01f * v;
            C[(size_t)r * N + c] = v;
        }
    }
}

// ---------------------------------------------------------------------------
// Flash-style fused kernel:
//   agg = softmax(mask(h @ h^T)) @ h      (mask: keep s>0, else -9e15 -> p=0)
//   out = log_softmax(alpha*agg + beta*h, axis=1)
// One CTA per 64 output rows; streams over 256 column blocks of 64 rows.
// Online softmax with running max initialized to 0 (valid: diag > 0, and any
// s<=0 contributes exactly 0 probability, matching exp(-9e15 - max) == 0).
// ---------------------------------------------------------------------------
#define QS_STRIDE 140   // 64 x 140 floats (pad: row delta of 4 rows -> bank +16)
#define KS_STRIDE 65    // Ks stored [d][n]: 128 x 65
#define PS_STRIDE 68    // Ps [m][n]: 64 x 68
#define SMEM_FLOATS (64*QS_STRIDE + 128*KS_STRIDE + 64*PS_STRIDE)  // 21632
#define SMEM_BYTES  (SMEM_FLOATS * 4)                               // 86528

__global__ __launch_bounds__(256) void flash_sim_kernel(
    const float* __restrict__ alpha, const float* __restrict__ beta,
    float* __restrict__ out)
{
    extern __shared__ float sm[];
    float* Qs = sm;                        // [64][140]  row-major [m][d]
    float* Ks = sm + 64 * QS_STRIDE;       // [128][65]  [d][n] (transposed K/V)
    float* Ps = Ks + 128 * KS_STRIDE;      // [64][68]   [m][n]

    const float* __restrict__ h = g_h;
    const int tid = threadIdx.x;
    const int ty = tid >> 4, tx = tid & 15;
    const int r0 = blockIdx.x * 64;

    // Load Q block (64 x 128)
    #pragma unroll
    for (int it = 0; it < 8; ++it) {
        int idx = it * 256 + tid;
        int r = idx >> 5;
        int c = (idx & 31) << 2;
        float4 v = *(const float4*)(h + (size_t)(r0 + r) * OD + c);
        *(float4*)&Qs[r * QS_STRIDE + c] = v;
    }

    float acc[4][8];
    float m[4], l[4];
    #pragma unroll
    for (int i = 0; i < 4; i++) {
        m[i] = 0.f; l[i] = 0.f;
        #pragma unroll
        for (int j = 0; j < 8; j++) acc[i][j] = 0.f;
    }

    for (int nb = 0; nb < NROWS / 64; ++nb) {
        const int c0 = nb * 64;
        __syncthreads();   // previous PV done reading Ks
        // Load K/V block transposed: Ks[d][n] = h[c0+n][d]
        #pragma unroll
        for (int it = 0; it < 8; ++it) {
            int idx = it * 256 + tid;
            int n = idx >> 5;
            int c = (idx & 31) << 2;
            float4 v = *(const float4*)(h + (size_t)(c0 + n) * OD + c);
            Ks[(c + 0) * KS_STRIDE + n] = v.x;
            Ks[(c + 1) * KS_STRIDE + n] = v.y;
            Ks[(c + 2) * KS_STRIDE + n] = v.z;
            Ks[(c + 3) * KS_STRIDE + n] = v.w;
        }
        __syncthreads();

        // S = Q @ K^T  (4x4 per thread, cols strided by 16)
        float s[4][4];
        #pragma unroll
        for (int i = 0; i < 4; i++)
            #pragma unroll
            for (int j = 0; j < 4; j++) s[i][j] = 0.f;

        const float* qbase = &Qs[(ty * 4) * QS_STRIDE];
        #pragma unroll 4
        for (int k = 0; k < OD; k++) {
            float qa[4], kb[4];
            #pragma unroll
            for (int i = 0; i < 4; i++) qa[i] = qbase[i * QS_STRIDE + k];
            #pragma unroll
            for (int j = 0; j < 4; j++) kb[j] = Ks[k * KS_STRIDE + tx + 16 * j];
            #pragma unroll
            for (int i = 0; i < 4; i++)
                #pragma unroll
                for (int j = 0; j < 4; j++)
                    s[i][j] = fmaf(qa[i], kb[j], s[i][j]);
        }

        // Online masked softmax per row
        #pragma unroll
        for (int i = 0; i < 4; i++) {
            float bm = 0.f;  // floor 0 == mask threshold; true row max > 0
            #pragma unroll
            for (int j = 0; j < 4; j++) bm = fmaxf(bm, s[i][j]);
            #pragma unroll
            for (int off = 8; off >= 1; off >>= 1)
                bm = fmaxf(bm, __shfl_xor_sync(0xffffffffu, bm, off));

            float mnew = fmaxf(m[i], bm);
            float sc = __expf(m[i] - mnew);
            float ps = 0.f;
            #pragma unroll
            for (int j = 0; j < 4; j++) {
                float p = (s[i][j] > 0.f) ? __expf(s[i][j] - mnew) : 0.f;
                s[i][j] = p;
                ps += p;
            }
            #pragma unroll
            for (int off = 8; off >= 1; off >>= 1)
                ps += __shfl_xor_sync(0xffffffffu, ps, off);

            l[i] = l[i] * sc + ps;
            m[i] = mnew;
            #pragma unroll
            for (int j = 0; j < 8; j++) acc[i][j] *= sc;
            #pragma unroll
            for (int j = 0; j < 4; j++)
                Ps[(ty * 4 + i) * PS_STRIDE + tx + 16 * j] = s[i][j];
        }
        __syncthreads();

        // O += P @ V   (V[n][d] == Ks[d][n])
        #pragma unroll 4
        for (int n = 0; n < 64; n++) {
            float pv[4], vv[8];
            #pragma unroll
            for (int i = 0; i < 4; i++) pv[i] = Ps[(ty * 4 + i) * PS_STRIDE + n];
            #pragma unroll
            for (int j = 0; j < 8; j++) vv[j] = Ks[(tx + 16 * j) * KS_STRIDE + n];
            #pragma unroll
            for (int i = 0; i < 4; i++)
                #pragma unroll
                for (int j = 0; j < 8; j++)
                    acc[i][j] = fmaf(pv[i], vv[j], acc[i][j]);
        }
    }

    // Epilogue: out = log_softmax(alpha*agg + beta*h) per row (128 cols)
    const float a_ = alpha[0], b_ = beta[0];
    #pragma unroll
    for (int i = 0; i < 4; i++) {
        int row = r0 + ty * 4 + i;
        float inv_l = 1.f / l[i];
        float v[8];
        float mx = -INFINITY;
        #pragma unroll
        for (int j = 0; j < 8; j++) {
            float hv = h[(size_t)row * OD + tx + 16 * j];
            v[j] = a_ * (acc[i][j] * inv_l) + b_ * hv;
            mx = fmaxf(mx, v[j]);
        }
        #pragma unroll
        for (int off = 8; off >= 1; off >>= 1)
            mx = fmaxf(mx, __shfl_xor_sync(0xffffffffu, mx, off));
        float se = 0.f;
        #pragma unroll
        for (int j = 0; j < 8; j++) se += expf(v[j] - mx);
        #pragma unroll
        for (int off = 8; off >= 1; off >>= 1)
            se += __shfl_xor_sync(0xffffffffu, se, off);
        float lse = mx + logf(se);
        #pragma unroll
        for (int j = 0; j < 8; j++)
            out[(size_t)row * OD + tx + 16 * j] = v[j] - lse;
    }
}

// ---------------------------------------------------------------------------
// Launch: inputs in metadata order:
// 0:x [N,512] f32, 1:g (unused), 2:W1 [512,256], 3:b1 [256],
// 4:W2 [256,128], 5:b2 [128], 6:alpha [1], 7:beta [1]
// ---------------------------------------------------------------------------
extern "C" void kernel_launch(void* const* d_in, const int* in_sizes, int n_in,
                              void* d_out, int out_size)
{
    (void)in_sizes; (void)n_in; (void)out_size;
    const float* x     = (const float*)d_in[0];
    const float* W1    = (const float*)d_in[2];
    const float* b1    = (const float*)d_in[3];
    const float* W2    = (const float*)d_in[4];
    const float* b2    = (const float*)d_in[5];
    const float* alpha = (const float*)d_in[6];
    const float* beta  = (const float*)d_in[7];
    float* out = (float*)d_out;

    float *h1p = nullptr, *hp = nullptr;
    cudaGetSymbolAddress((void**)&h1p, g_h1);
    cudaGetSymbolAddress((void**)&hp,  g_h);

    dim3 g1(HIDD / 64, NROWS / 64);   // 4 x 256
    gemm_bias_kernel<true><<<g1, 256>>>(x, W1, b1, h1p, NROWS, HIDD, IND);

    dim3 g2(OD / 64, NROWS / 64);     // 2 x 256
    gemm_bias_kernel<false><<<g2, 256>>>(h1p, W2, b2, hp, NROWS, OD, HIDD);

    cudaFuncSetAttribute(flash_sim_kernel,
                         cudaFuncAttributeMaxDynamicSharedMemorySize, SMEM_BYTES);
    flash_sim_kernel<<<NROWS / 64, 256, SMEM_BYTES>>>(alpha, beta, out);
}

// round 3
// speedup vs baseline: 6.1989x; 6.1989x over previous
#include <cuda_runtime.h>
#include <cuda_bf16.h>
#include <cstdint>
#include <math.h>

// Problem dims (fixed per reference)
#define NROWS 16384
#define IND   512
#define HIDD  256
#define OD    128
#define NB    (NROWS / 128)

// Scratch (device globals; no allocations allowed)
__device__ float g_h1[NROWS * HIDD];            // after linear1 + leaky
__device__ float g_h [NROWS * OD];              // after linear2 (fp32, epilogue)
__device__ __nv_bfloat16 g_hb[NROWS * OD];      // bf16 h [N][128]

// ===========================================================================
// PTX helpers (baseline sm_80+ features only: cp.async, ldmatrix, mma.sync)
// ===========================================================================
__device__ __forceinline__ uint32_t smem_to_u32(const void* p) {
    uint32_t a;
    asm("{ .reg .u64 t; cvta.to.shared.u64 t, %1; cvt.u32.u64 %0, t; }"
        : "=r"(a) : "l"(p));
    return a;
}

__device__ __forceinline__ void cp_async16(uint32_t dst, const void* src) {
    asm volatile("cp.async.cg.shared.global [%0], [%1], 16;"
                 :: "r"(dst), "l"(src));
}
#define CP_COMMIT asm volatile("cp.async.commit_group;" ::: "memory")
#define CP_WAIT0  asm volatile("cp.async.wait_group 0;" ::: "memory")
#define CP_WAIT1  asm volatile("cp.async.wait_group 1;" ::: "memory")

__device__ __forceinline__ void ldsm_x4(uint32_t* r, uint32_t addr) {
    asm volatile("ldmatrix.sync.aligned.m8n8.x4.shared.b16 {%0,%1,%2,%3}, [%4];"
                 : "=r"(r[0]), "=r"(r[1]), "=r"(r[2]), "=r"(r[3]) : "r"(addr));
}
__device__ __forceinline__ void ldsm_x4_t(uint32_t* r, uint32_t addr) {
    asm volatile("ldmatrix.sync.aligned.m8n8.x4.trans.shared.b16 {%0,%1,%2,%3}, [%4];"
                 : "=r"(r[0]), "=r"(r[1]), "=r"(r[2]), "=r"(r[3]) : "r"(addr));
}

// D += A@B, m16n8k16, bf16 in, fp32 acc
__device__ __forceinline__ void mma16816(float* c, const uint32_t* a,
                                         const uint32_t b0, const uint32_t b1) {
    asm volatile(
        "mma.sync.aligned.m16n8k16.row.col.f32.bf16.bf16.f32 "
        "{%0,%1,%2,%3}, {%4,%5,%6,%7}, {%8,%9}, {%0,%1,%2,%3};"
        : "+f"(c[0]), "+f"(c[1]), "+f"(c[2]), "+f"(c[3])
        : "r"(a[0]), "r"(a[1]), "r"(a[2]), "r"(a[3]), "r"(b0), "r"(b1));
}

// pack two f32 -> bf16x2 (lo = second operand)
__device__ __forceinline__ uint32_t pack_bf16x2(float hi, float lo) {
    uint32_t d;
    asm("cvt.rn.bf16x2.f32 %0, %1, %2;" : "=r"(d) : "f"(hi), "f"(lo));
    return d;
}

// ===========================================================================
// GEMM: C = A@B + bias, optional LeakyReLU, optional bf16 copy of C
// ===========================================================================
template<bool LEAKY>
__global__ __launch_bounds__(256) void gemm_bias_kernel(
    const float* __restrict__ A, const float* __restrict__ B,
    const float* __restrict__ bias, float* __restrict__ C,
    __nv_bfloat16* __restrict__ Cb,
    int M, int N, int K)
{
    __shared__ float As[16][65];
    __shared__ float Bs[16][64];

    const int tid = threadIdx.x;
    const int ty = tid >> 4, tx = tid & 15;
    const int m0 = blockIdx.y * 64, n0 = blockIdx.x * 64;

    float acc[4][4];
    #pragma unroll
    for (int i = 0; i < 4; i++)
        #pragma unroll
        for (int j = 0; j < 4; j++) acc[i][j] = 0.f;

    const int ar = tid >> 2, ak = (tid & 3) << 2;
    const int bk = tid >> 4, bn = (tid & 15) << 2;

    for (int k0 = 0; k0 < K; k0 += 16) {
        float4 av = *(const float4*)(A + (size_t)(m0 + ar) * K + k0 + ak);
        As[ak + 0][ar] = av.x;
        As[ak + 1][ar] = av.y;
        As[ak + 2][ar] = av.z;
        As[ak + 3][ar] = av.w;
        float4 bv = *(const float4*)(B + (size_t)(k0 + bk) * N + n0 + bn);
        *(float4*)&Bs[bk][bn] = bv;
        __syncthreads();

        #pragma unroll
        for (int k = 0; k < 16; k++) {
            float ra[4], rb[4];
            #pragma unroll
            for (int i = 0; i < 4; i++) ra[i] = As[k][ty * 4 + i];
            #pragma unroll
            for (int j = 0; j < 4; j++) rb[j] = Bs[k][tx + 16 * j];
            #pragma unroll
            for (int i = 0; i < 4; i++)
                #pragma unroll
                for (int j = 0; j < 4; j++)
                    acc[i][j] = fmaf(ra[i], rb[j], acc[i][j]);
        }
        __syncthreads();
    }

    #pragma unroll
    for (int j = 0; j < 4; j++) {
        int c = n0 + tx + 16 * j;
        float bb = bias[c];
        #pragma unroll
        for (int i = 0; i < 4; i++) {
            int r = m0 + ty * 4 + i;
            float v = acc[i][j] + bb;
            if (LEAKY) v = (v >= 0.f) ? v : 0.01f * v;
            C[(size_t)r * N + c] = v;
            if (Cb) Cb[(size_t)r * N + c] = __float2bfloat16(v);
        }
    }
}

// ===========================================================================
// HMMA flash similarity kernel (mma.sync bf16).
//   One CTA = 128 Q rows (8 warps x 16 rows), streams 128 key-blocks of 128.
//   S = Q@K^T; p = (s>0)?exp(s):0 (mask floor 0, no rescale needed);
//   O += P@V accumulated in registers across all blocks;
//   out = log_softmax(alpha*O/l + beta*h).
//   K tile doubles as V tile (same data): non-trans ldmatrix for K^T frags,
//   trans ldmatrix for V frags.
// ===========================================================================
#define ROW_BYTES 272                    // 128 bf16 padded to 136 (conflict-free ldsm)
#define BUF_BYTES (128 * ROW_BYTES)      // 34816
#define FLASH_SMEM (2 * BUF_BYTES)       // 69632

__device__ __forceinline__ void load_tile(uint32_t dbase,
                                          const __nv_bfloat16* src, int tid) {
    #pragma unroll
    for (int it = 0; it < 8; it++) {
        int c = it * 256 + tid;
        int row = c >> 4, col = c & 15;
        cp_async16(dbase + row * ROW_BYTES + col * 16, src + row * OD + col * 8);
    }
}

__global__ __launch_bounds__(256, 1)
void flash_hmma_kernel(const __nv_bfloat16* __restrict__ hb,
                       const float* __restrict__ h,
                       const float* __restrict__ alpha,
                       const float* __restrict__ beta,
                       float* __restrict__ out)
{
    extern __shared__ char smem[];
    const uint32_t sbase = smem_to_u32(smem);
    const int tid = threadIdx.x;
    const int wid = tid >> 5, lane = tid & 31;
    const int r0 = blockIdx.x * 128;

    // ---- Stage Q tile into buf0, capture A-fragments in registers ----
    load_tile(sbase, hb + (size_t)r0 * OD, tid);
    CP_COMMIT; CP_WAIT0;
    __syncthreads();

    uint32_t qf[8][4];
    {
        const int qr = wid * 16 + (lane & 15);
        const int qc = (lane >> 4) << 3;
        #pragma unroll
        for (int kt = 0; kt < 8; kt++)
            ldsm_x4(qf[kt], sbase + qr * ROW_BYTES + (kt * 16 + qc) * 2);
    }
    __syncthreads();

    // ---- Prefetch key-block 0 into buf0 ----
    load_tile(sbase, hb, tid);
    CP_COMMIT;

    float oacc[16][4];
    #pragma unroll
    for (int i = 0; i < 16; i++)
        #pragma unroll
        for (int j = 0; j < 4; j++) oacc[i][j] = 0.f;
    float l0 = 0.f, l1 = 0.f;

    // ldmatrix lane->address components (constant per thread)
    const int brow = lane & 15;                           // non-trans rows
    const int bcol = (lane >> 4) << 3;                    // non-trans col half
    const int vrow = ((lane >> 4) << 3) + (lane & 7);     // trans rows
    const int vcol = ((lane >> 3) & 1) << 3;              // trans col half

    for (int nb = 0; nb < NB; nb++) {
        const uint32_t cur = sbase + (uint32_t)(nb & 1) * BUF_BYTES;
        if (nb + 1 < NB) {
            load_tile(sbase + (uint32_t)((nb + 1) & 1) * BUF_BYTES,
                      hb + (size_t)(nb + 1) * 128 * OD, tid);
            CP_COMMIT; CP_WAIT1;
        } else {
            CP_WAIT0;
        }
        __syncthreads();

        // ---- S = Q @ K^T ----
        float sacc[16][4];
        #pragma unroll
        for (int i = 0; i < 16; i++)
            #pragma unroll
            for (int j = 0; j < 4; j++) sacc[i][j] = 0.f;

        #pragma unroll
        for (int jp = 0; jp < 8; jp++) {
            const uint32_t rbase = cur + (jp * 16 + brow) * ROW_BYTES;
            #pragma unroll
            for (int kt = 0; kt < 8; kt++) {
                uint32_t r[4];
                ldsm_x4(r, rbase + (kt * 16 + bcol) * 2);
                mma16816(sacc[2 * jp],     qf[kt], r[0], r[2]);
                mma16816(sacc[2 * jp + 1], qf[kt], r[1], r[3]);
            }
        }

        // ---- masked exp + pack to A-fragments of P ----
        uint32_t pf[16][2];
        #pragma unroll
        for (int nt = 0; nt < 16; nt++) {
            float p0 = sacc[nt][0] > 0.f ? __expf(sacc[nt][0]) : 0.f;
            float p1 = sacc[nt][1] > 0.f ? __expf(sacc[nt][1]) : 0.f;
            float p2 = sacc[nt][2] > 0.f ? __expf(sacc[nt][2]) : 0.f;
            float p3 = sacc[nt][3] > 0.f ? __expf(sacc[nt][3]) : 0.f;
            l0 += p0 + p1;
            l1 += p2 + p3;
            pf[nt][0] = pack_bf16x2(p1, p0);
            pf[nt][1] = pack_bf16x2(p3, p2);
        }

        // ---- O += P @ V (trans ldmatrix of same tile) ----
        #pragma unroll
        for (int kt = 0; kt < 8; kt++) {
            uint32_t af[4] = { pf[2 * kt][0],     pf[2 * kt][1],
                               pf[2 * kt + 1][0], pf[2 * kt + 1][1] };
            const uint32_t rbase = cur + (kt * 16 + vrow) * ROW_BYTES;
            #pragma unroll
            for (int jp = 0; jp < 8; jp++) {
                uint32_t r[4];
                ldsm_x4_t(r, rbase + (jp * 16 + vcol) * 2);
                mma16816(oacc[2 * jp],     af, r[0], r[2]);
                mma16816(oacc[2 * jp + 1], af, r[1], r[3]);
            }
        }
        __syncthreads();
    }

    // ---- reduce row sums across the quad (lanes sharing a row) ----
    l0 += __shfl_xor_sync(0xffffffffu, l0, 1);
    l0 += __shfl_xor_sync(0xffffffffu, l0, 2);
    l1 += __shfl_xor_sync(0xffffffffu, l1, 1);
    l1 += __shfl_xor_sync(0xffffffffu, l1, 2);

    // ---- epilogue: v = alpha*O/l + beta*h, then log_softmax per row ----
    const float a_ = alpha[0], b_ = beta[0];
    const float s0 = a_ / l0, s1 = a_ / l1;
    const int g = lane >> 2, t = lane & 3;
    const int row_lo = r0 + wid * 16 + g;
    const int row_hi = row_lo + 8;

    float mx0 = -INFINITY, mx1 = -INFINITY;
    #pragma unroll
    for (int nt = 0; nt < 16; nt++) {
        const int col = nt * 8 + 2 * t;
        float2 hlo = *(const float2*)(h + (size_t)row_lo * OD + col);
        float2 hhi = *(const float2*)(h + (size_t)row_hi * OD + col);
        float v0 = s0 * oacc[nt][0] + b_ * hlo.x;
        float v1 = s0 * oacc[nt][1] + b_ * hlo.y;
        float v2 = s1 * oacc[nt][2] + b_ * hhi.x;
        float v3 = s1 * oacc[nt][3] + b_ * hhi.y;
        oacc[nt][0] = v0; oacc[nt][1] = v1;
        oacc[nt][2] = v2; oacc[nt][3] = v3;
        mx0 = fmaxf(mx0, fmaxf(v0, v1));
        mx1 = fmaxf(mx1, fmaxf(v2, v3));
    }
    mx0 = fmaxf(mx0, __shfl_xor_sync(0xffffffffu, mx0, 1));
    mx0 = fmaxf(mx0, __shfl_xor_sync(0xffffffffu, mx0, 2));
    mx1 = fmaxf(mx1, __shfl_xor_sync(0xffffffffu, mx1, 1));
    mx1 = fmaxf(mx1, __shfl_xor_sync(0xffffffffu, mx1, 2));

    float se0 = 0.f, se1 = 0.f;
    #pragma unroll
    for (int nt = 0; nt < 16; nt++) {
        se0 += __expf(oacc[nt][0] - mx0) + __expf(oacc[nt][1] - mx0);
        se1 += __expf(oacc[nt][2] - mx1) + __expf(oacc[nt][3] - mx1);
    }
    se0 += __shfl_xor_sync(0xffffffffu, se0, 1);
    se0 += __shfl_xor_sync(0xffffffffu, se0, 2);
    se1 += __shfl_xor_sync(0xffffffffu, se1, 1);
    se1 += __shfl_xor_sync(0xffffffffu, se1, 2);
    const float lse0 = mx0 + logf(se0);
    const float lse1 = mx1 + logf(se1);

    #pragma unroll
    for (int nt = 0; nt < 16; nt++) {
        const int col = nt * 8 + 2 * t;
        *(float2*)(out + (size_t)row_lo * OD + col) =
            make_float2(oacc[nt][0] - lse0, oacc[nt][1] - lse0);
        *(float2*)(out + (size_t)row_hi * OD + col) =
            make_float2(oacc[nt][2] - lse1, oacc[nt][3] - lse1);
    }
}

// ===========================================================================
// Launch. Inputs: 0:x 1:g 2:W1 3:b1 4:W2 5:b2 6:alpha 7:beta
// ===========================================================================
extern "C" void kernel_launch(void* const* d_in, const int* in_sizes, int n_in,
                              void* d_out, int out_size)
{
    (void)in_sizes; (void)n_in; (void)out_size;
    const float* x     = (const float*)d_in[0];
    const float* W1    = (const float*)d_in[2];
    const float* b1    = (const float*)d_in[3];
    const float* W2    = (const float*)d_in[4];
    const float* b2    = (const float*)d_in[5];
    const float* alpha = (const float*)d_in[6];
    const float* beta  = (const float*)d_in[7];
    float* out = (float*)d_out;

    float *h1p = nullptr, *hp = nullptr;
    __nv_bfloat16 *hbp = nullptr;
    cudaGetSymbolAddress((void**)&h1p, g_h1);
    cudaGetSymbolAddress((void**)&hp,  g_h);
    cudaGetSymbolAddress((void**)&hbp, g_hb);

    dim3 g1(HIDD / 64, NROWS / 64);
    gemm_bias_kernel<true><<<g1, 256>>>(x, W1, b1, h1p, nullptr,
                                        NROWS, HIDD, IND);

    dim3 g2(OD / 64, NROWS / 64);
    gemm_bias_kernel<false><<<g2, 256>>>(h1p, W2, b2, hp, hbp,
                                         NROWS, OD, HIDD);

    cudaFuncSetAttribute(flash_hmma_kernel,
                         cudaFuncAttributeMaxDynamicSharedMemorySize, FLASH_SMEM);
    flash_hmma_kernel<<<NROWS / 128, 256, FLASH_SMEM>>>(hbp, hp, alpha, beta, out);
}

// round 4
// speedup vs baseline: 8.3046x; 1.3397x over previous
#include <cuda_runtime.h>
#include <cuda_bf16.h>
#include <cstdint>
#include <math.h>

// Problem dims (fixed per reference)
#define NROWS 16384
#define IND   512
#define HIDD  256
#define OD    128
#define NB    (NROWS / 128)

// Scratch (device globals; no allocations allowed)
__device__ __nv_bfloat16 g_xb [NROWS * IND];    // bf16 x
__device__ __nv_bfloat16 g_w1b[IND * HIDD];     // bf16 W1
__device__ __nv_bfloat16 g_w2b[HIDD * OD];      // bf16 W2
__device__ __nv_bfloat16 g_h1b[NROWS * HIDD];   // bf16 h1 (after leaky)
__device__ float         g_h  [NROWS * OD];     // fp32 h (epilogue)
__device__ __nv_bfloat16 g_hb [NROWS * OD];     // bf16 h

// ===========================================================================
// PTX helpers (sm_80+ baseline only)
// ===========================================================================
__device__ __forceinline__ uint32_t smem_to_u32(const void* p) {
    uint32_t a;
    asm("{ .reg .u64 t; cvta.to.shared.u64 t, %1; cvt.u32.u64 %0, t; }"
        : "=r"(a) : "l"(p));
    return a;
}

__device__ __forceinline__ void cp_async16(uint32_t dst, const void* src) {
    asm volatile("cp.async.cg.shared.global [%0], [%1], 16;"
                 :: "r"(dst), "l"(src));
}
#define CP_COMMIT asm volatile("cp.async.commit_group;" ::: "memory")
#define CP_WAIT0  asm volatile("cp.async.wait_group 0;" ::: "memory")

__device__ __forceinline__ void ldsm_x4(uint32_t* r, uint32_t addr) {
    asm volatile("ldmatrix.sync.aligned.m8n8.x4.shared.b16 {%0,%1,%2,%3}, [%4];"
                 : "=r"(r[0]), "=r"(r[1]), "=r"(r[2]), "=r"(r[3]) : "r"(addr));
}
__device__ __forceinline__ void ldsm_x4_t(uint32_t* r, uint32_t addr) {
    asm volatile("ldmatrix.sync.aligned.m8n8.x4.trans.shared.b16 {%0,%1,%2,%3}, [%4];"
                 : "=r"(r[0]), "=r"(r[1]), "=r"(r[2]), "=r"(r[3]) : "r"(addr));
}
__device__ __forceinline__ uint32_t movm(uint32_t a) {
    uint32_t d;
    asm("movmatrix.sync.aligned.m8n8.trans.b16 %0, %1;" : "=r"(d) : "r"(a));
    return d;
}

// D += A@B, m16n8k16, bf16 in, fp32 acc
__device__ __forceinline__ void mma16816(float* c, const uint32_t* a,
                                         const uint32_t b0, const uint32_t b1) {
    asm volatile(
        "mma.sync.aligned.m16n8k16.row.col.f32.bf16.bf16.f32 "
        "{%0,%1,%2,%3}, {%4,%5,%6,%7}, {%8,%9}, {%0,%1,%2,%3};"
        : "+f"(c[0]), "+f"(c[1]), "+f"(c[2]), "+f"(c[3])
        : "r"(a[0]), "r"(a[1]), "r"(a[2]), "r"(a[3]), "r"(b0), "r"(b1));
}

__device__ __forceinline__ uint32_t pack_bf16x2(float hi, float lo) {
    uint32_t d;
    asm("cvt.rn.bf16x2.f32 %0, %1, %2;" : "=r"(d) : "f"(hi), "f"(lo));
    return d;
}

// ===========================================================================
// fp32 -> bf16 conversion (vectorized x4)
// ===========================================================================
__global__ __launch_bounds__(256) void cvt_bf16_kernel(
    const float* __restrict__ in, __nv_bfloat16* __restrict__ out, int n4)
{
    int i = blockIdx.x * 256 + threadIdx.x;
    if (i < n4) {
        float4 v = ((const float4*)in)[i];
        ((uint2*)out)[i] = make_uint2(pack_bf16x2(v.y, v.x),
                                      pack_bf16x2(v.w, v.z));
    }
}

// ===========================================================================
// bf16 HMMA GEMM: C = A(bf16)@B(bf16) + bias, optional LeakyReLU.
// CTA = 128x128 tile, 8 warps x 16 rows, K-chunks of 64, double-buffered.
// Writes bf16 Cb always; fp32 C if WRITE_F32.
// ===========================================================================
#define GA_STRIDE 144                 // 64 bf16 row + pad
#define GA_BUF    (128 * GA_STRIDE)   // 18432
#define GB_STRIDE 272                 // 128 bf16 row + pad
#define GB_BUF    (64 * GB_STRIDE)    // 17408
#define GEMM_SMEM (2 * GA_BUF + 2 * GB_BUF)  // 71680

template<int KDIM, int NGLOB, bool LEAKY, bool WRITE_F32>
__global__ __launch_bounds__(256, 2) void hgemm_kernel(
    const __nv_bfloat16* __restrict__ A, const __nv_bfloat16* __restrict__ B,
    const float* __restrict__ bias, float* __restrict__ C,
    __nv_bfloat16* __restrict__ Cb)
{
    extern __shared__ char smem[];
    const uint32_t sb = smem_to_u32(smem);
    const int tid = threadIdx.x;
    const int wid = tid >> 5, lane = tid & 31;
    const int m0 = blockIdx.y * 128, n0 = blockIdx.x * 128;

    const uint32_t sA[2] = { sb, sb + GA_BUF };
    const uint32_t sB[2] = { sb + 2 * GA_BUF, sb + 2 * GA_BUF + GB_BUF };

    float acc[16][4];
    #pragma unroll
    for (int i = 0; i < 16; i++)
        #pragma unroll
        for (int j = 0; j < 4; j++) acc[i][j] = 0.f;

    // ldmatrix lane address components
    const int brow  = lane & 15;
    const int bcolb = ((lane >> 4) << 3) * 2;
    const int vrow  = ((lane >> 4) << 3) + (lane & 7);
    const int vcolb = (((lane >> 3) & 1) << 3) * 2;

    // fill chunk k0 into buffer bi
    auto fill = [&](int bi, int k0) {
        #pragma unroll
        for (int it = 0; it < 4; it++) {
            int c = it * 256 + tid;
            int r = c >> 3, c8 = c & 7;
            cp_async16(sA[bi] + r * GA_STRIDE + c8 * 16,
                       A + (size_t)(m0 + r) * KDIM + k0 + c8 * 8);
        }
        #pragma unroll
        for (int it = 0; it < 4; it++) {
            int c = it * 256 + tid;
            int r = c >> 4, cc = c & 15;
            cp_async16(sB[bi] + r * GB_STRIDE + cc * 16,
                       B + (size_t)(k0 + r) * NGLOB + n0 + cc * 8);
        }
        CP_COMMIT;
    };

    fill(0, 0);
    constexpr int NC = KDIM / 64;

    for (int ck = 0; ck < NC; ck++) {
        CP_WAIT0;
        __syncthreads();
        if (ck + 1 < NC) fill((ck + 1) & 1, (ck + 1) * 64);

        const uint32_t cA = sA[ck & 1], cB = sB[ck & 1];

        uint32_t af[4][4];
        const uint32_t ab = cA + (wid * 16 + brow) * GA_STRIDE + bcolb;
        #pragma unroll
        for (int kt = 0; kt < 4; kt++) ldsm_x4(af[kt], ab + kt * 32);

        #pragma unroll
        for (int kt = 0; kt < 4; kt++) {
            const uint32_t rb = cB + (kt * 16 + vrow) * GB_STRIDE + vcolb;
            #pragma unroll
            for (int jp = 0; jp < 8; jp++) {
                uint32_t r[4];
                ldsm_x4_t(r, rb + jp * 32);
                mma16816(acc[2 * jp],     af[kt], r[0], r[2]);
                mma16816(acc[2 * jp + 1], af[kt], r[1], r[3]);
            }
        }
    }

    // epilogue
    const int g = lane >> 2, t = lane & 3;
    const int row_lo = m0 + wid * 16 + g;
    const int row_hi = row_lo + 8;
    #pragma unroll
    for (int nt = 0; nt < 16; nt++) {
        const int col = n0 + nt * 8 + 2 * t;
        const float bb0 = bias[col], bb1 = bias[col + 1];
        float v0 = acc[nt][0] + bb0, v1 = acc[nt][1] + bb1;
        float v2 = acc[nt][2] + bb0, v3 = acc[nt][3] + bb1;
        if (LEAKY) {
            v0 = v0 >= 0.f ? v0 : 0.01f * v0;
            v1 = v1 >= 0.f ? v1 : 0.01f * v1;
            v2 = v2 >= 0.f ? v2 : 0.01f * v2;
            v3 = v3 >= 0.f ? v3 : 0.01f * v3;
        }
        if (WRITE_F32) {
            *(float2*)(C + (size_t)row_lo * NGLOB + col) = make_float2(v0, v1);
            *(float2*)(C + (size_t)row_hi * NGLOB + col) = make_float2(v2, v3);
        }
        *(uint32_t*)(Cb + (size_t)row_lo * NGLOB + col) = pack_bf16x2(v1, v0);
        *(uint32_t*)(Cb + (size_t)row_hi * NGLOB + col) = pack_bf16x2(v3, v2);
    }
}

// ===========================================================================
// HMMA flash similarity kernel, fused single-pass per 16-row n-block:
//   S block -> elementwise masked exp -> P fragments -> PV via movmatrix
//   (tile read from smem ONCE; PV B-frags are in-register transposes).
// ===========================================================================
#define ROW_BYTES 272
#define BUF_BYTES (128 * ROW_BYTES)
#define FLASH_SMEM (2 * BUF_BYTES)   // 69632

__device__ __forceinline__ void load_tile(uint32_t dbase,
                                          const __nv_bfloat16* src, int tid) {
    #pragma unroll
    for (int it = 0; it < 8; it++) {
        int c = it * 256 + tid;
        int row = c >> 4, col = c & 15;
        cp_async16(dbase + row * ROW_BYTES + col * 16, src + row * OD + col * 8);
    }
    CP_COMMIT;
}

__global__ __launch_bounds__(256, 1)
void flash_hmma_kernel(const __nv_bfloat16* __restrict__ hb,
                       const float* __restrict__ h,
                       const float* __restrict__ alpha,
                       const float* __restrict__ beta,
                       float* __restrict__ out)
{
    extern __shared__ char smem[];
    const uint32_t sbase = smem_to_u32(smem);
    const int tid = threadIdx.x;
    const int wid = tid >> 5, lane = tid & 31;
    const int r0 = blockIdx.x * 128;

    const int brow  = lane & 15;
    const int bcolb = ((lane >> 4) << 3) * 2;

    // ---- Stage Q tile, capture A-fragments ----
    load_tile(sbase, hb + (size_t)r0 * OD, tid);
    CP_WAIT0;
    __syncthreads();

    uint32_t qf[8][4];
    {
        const uint32_t qb = sbase + (wid * 16 + brow) * ROW_BYTES + bcolb;
        #pragma unroll
        for (int kt = 0; kt < 8; kt++) ldsm_x4(qf[kt], qb + kt * 32);
    }
    __syncthreads();

    // ---- Prefetch key-block 0 into buf0 ----
    load_tile(sbase, hb, tid);

    float oacc[16][4];
    #pragma unroll
    for (int i = 0; i < 16; i++)
        #pragma unroll
        for (int j = 0; j < 4; j++) oacc[i][j] = 0.f;
    float l0 = 0.f, l1 = 0.f;

    for (int kb = 0; kb < NB; kb++) {
        CP_WAIT0;
        __syncthreads();
        if (kb + 1 < NB)
            load_tile(sbase + (uint32_t)((kb + 1) & 1) * BUF_BYTES,
                      hb + (size_t)(kb + 1) * 128 * OD, tid);

        const uint32_t cur = sbase + (uint32_t)(kb & 1) * BUF_BYTES;

        #pragma unroll
        for (int nbk = 0; nbk < 8; nbk++) {
            // load 16 n-rows x 128 d-cols fragments (ONCE)
            uint32_t r[8][4];
            const uint32_t rb = cur + (nbk * 16 + brow) * ROW_BYTES + bcolb;
            #pragma unroll
            for (int dk = 0; dk < 8; dk++) ldsm_x4(r[dk], rb + dk * 32);

            // S = Q @ K^T for this n-block
            float s0[4] = {0.f, 0.f, 0.f, 0.f};
            float s1[4] = {0.f, 0.f, 0.f, 0.f};
            #pragma unroll
            for (int dk = 0; dk < 8; dk++) {
                mma16816(s0, qf[dk], r[dk][0], r[dk][2]);
                mma16816(s1, qf[dk], r[dk][1], r[dk][3]);
            }

            // masked exp (elementwise; no row-max needed), pack P A-frags
            float p00 = s0[0] > 0.f ? __expf(s0[0]) : 0.f;
            float p01 = s0[1] > 0.f ? __expf(s0[1]) : 0.f;
            float p02 = s0[2] > 0.f ? __expf(s0[2]) : 0.f;
            float p03 = s0[3] > 0.f ? __expf(s0[3]) : 0.f;
            float p10 = s1[0] > 0.f ? __expf(s1[0]) : 0.f;
            float p11 = s1[1] > 0.f ? __expf(s1[1]) : 0.f;
            float p12 = s1[2] > 0.f ? __expf(s1[2]) : 0.f;
            float p13 = s1[3] > 0.f ? __expf(s1[3]) : 0.f;
            l0 += (p00 + p01) + (p10 + p11);
            l1 += (p02 + p03) + (p12 + p13);
            uint32_t af[4] = { pack_bf16x2(p01, p00), pack_bf16x2(p03, p02),
                               pack_bf16x2(p11, p10), pack_bf16x2(p13, p12) };

            // O += P @ V ; B-frags via in-register transpose of r
            #pragma unroll
            for (int dk = 0; dk < 8; dk++) {
                mma16816(oacc[2 * dk],     af, movm(r[dk][0]), movm(r[dk][1]));
                mma16816(oacc[2 * dk + 1], af, movm(r[dk][2]), movm(r[dk][3]));
            }
        }
    }

    // ---- reduce row sums across the quad ----
    l0 += __shfl_xor_sync(0xffffffffu, l0, 1);
    l0 += __shfl_xor_sync(0xffffffffu, l0, 2);
    l1 += __shfl_xor_sync(0xffffffffu, l1, 1);
    l1 += __shfl_xor_sync(0xffffffffu, l1, 2);

    // ---- epilogue: v = alpha*O/l + beta*h, then log_softmax per row ----
    const float a_ = alpha[0], b_ = beta[0];
    const float s0_ = a_ / l0, s1_ = a_ / l1;
    const int g = lane >> 2, t = lane & 3;
    const int row_lo = r0 + wid * 16 + g;
    const int row_hi = row_lo + 8;

    float mx0 = -INFINITY, mx1 = -INFINITY;
    #pragma unroll
    for (int nt = 0; nt < 16; nt++) {
        const int col = nt * 8 + 2 * t;
        float2 hlo = *(const float2*)(h + (size_t)row_lo * OD + col);
        float2 hhi = *(const float2*)(h + (size_t)row_hi * OD + col);
        float v0 = s0_ * oacc[nt][0] + b_ * hlo.x;
        float v1 = s0_ * oacc[nt][1] + b_ * hlo.y;
        float v2 = s1_ * oacc[nt][2] + b_ * hhi.x;
        float v3 = s1_ * oacc[nt][3] + b_ * hhi.y;
        oacc[nt][0] = v0; oacc[nt][1] = v1;
        oacc[nt][2] = v2; oacc[nt][3] = v3;
        mx0 = fmaxf(mx0, fmaxf(v0, v1));
        mx1 = fmaxf(mx1, fmaxf(v2, v3));
    }
    mx0 = fmaxf(mx0, __shfl_xor_sync(0xffffffffu, mx0, 1));
    mx0 = fmaxf(mx0, __shfl_xor_sync(0xffffffffu, mx0, 2));
    mx1 = fmaxf(mx1, __shfl_xor_sync(0xffffffffu, mx1, 1));
    mx1 = fmaxf(mx1, __shfl_xor_sync(0xffffffffu, mx1, 2));

    float se0 = 0.f, se1 = 0.f;
    #pragma unroll
    for (int nt = 0; nt < 16; nt++) {
        se0 += __expf(oacc[nt][0] - mx0) + __expf(oacc[nt][1] - mx0);
        se1 += __expf(oacc[nt][2] - mx1) + __expf(oacc[nt][3] - mx1);
    }
    se0 += __shfl_xor_sync(0xffffffffu, se0, 1);
    se0 += __shfl_xor_sync(0xffffffffu, se0, 2);
    se1 += __shfl_xor_sync(0xffffffffu, se1, 1);
    se1 += __shfl_xor_sync(0xffffffffu, se1, 2);
    const float lse0 = mx0 + logf(se0);
    const float lse1 = mx1 + logf(se1);

    #pragma unroll
    for (int nt = 0; nt < 16; nt++) {
        const int col = nt * 8 + 2 * t;
        *(float2*)(out + (size_t)row_lo * OD + col) =
            make_float2(oacc[nt][0] - lse0, oacc[nt][1] - lse0);
        *(float2*)(out + (size_t)row_hi * OD + col) =
            make_float2(oacc[nt][2] - lse1, oacc[nt][3] - lse1);
    }
}

// ===========================================================================
// Launch. Inputs: 0:x 1:g 2:W1 3:b1 4:W2 5:b2 6:alpha 7:beta
// ===========================================================================
extern "C" void kernel_launch(void* const* d_in, const int* in_sizes, int n_in,
                              void* d_out, int out_size)
{
    (void)in_sizes; (void)n_in; (void)out_size;
    const float* x     = (const float*)d_in[0];
    const float* W1    = (const float*)d_in[2];
    const float* b1    = (const float*)d_in[3];
    const float* W2    = (const float*)d_in[4];
    const float* b2    = (const float*)d_in[5];
    const float* alpha = (const float*)d_in[6];
    const float* beta  = (const float*)d_in[7];
    float* out = (float*)d_out;

    __nv_bfloat16 *xb, *w1b, *w2b, *h1b, *hbp;
    float *hp;
    cudaGetSymbolAddress((void**)&xb,  g_xb);
    cudaGetSymbolAddress((void**)&w1b, g_w1b);
    cudaGetSymbolAddress((void**)&w2b, g_w2b);
    cudaGetSymbolAddress((void**)&h1b, g_h1b);
    cudaGetSymbolAddress((void**)&hp,  g_h);
    cudaGetSymbolAddress((void**)&hbp, g_hb);

    // fp32 -> bf16 conversions
    cvt_bf16_kernel<<<(NROWS * IND / 4 + 255) / 256, 256>>>(x,  xb,  NROWS * IND / 4);
    cvt_bf16_kernel<<<(IND * HIDD / 4 + 255) / 256, 256>>>(W1, w1b, IND * HIDD / 4);
    cvt_bf16_kernel<<<(HIDD * OD / 4 + 255) / 256, 256>>>(W2, w2b, HIDD * OD / 4);

    // gemm1: h1 = leaky(x@W1 + b1), bf16 out only
    cudaFuncSetAttribute(hgemm_kernel<IND, HIDD, true, false>,
                         cudaFuncAttributeMaxDynamicSharedMemorySize, GEMM_SMEM);
    hgemm_kernel<IND, HIDD, true, false>
        <<<dim3(HIDD / 128, NROWS / 128), 256, GEMM_SMEM>>>(
            xb, w1b, b1, nullptr, h1b);

    // gemm2: h = h1@W2 + b2, fp32 + bf16 out
    cudaFuncSetAttribute(hgemm_kernel<HIDD, OD, false, true>,
                         cudaFuncAttributeMaxDynamicSharedMemorySize, GEMM_SMEM);
    hgemm_kernel<HIDD, OD, false, true>
        <<<dim3(OD / 128, NROWS / 128), 256, GEMM_SMEM>>>(
            h1b, w2b, b2, hp, hbp);

    // flash attention-like similarity aggregation + log_softmax
    cudaFuncSetAttribute(flash_hmma_kernel,
                         cudaFuncAttributeMaxDynamicSharedMemorySize, FLASH_SMEM);
    flash_hmma_kernel<<<NROWS / 128, 256, FLASH_SMEM>>>(hbp, hp, alpha, beta, out);
}